// round 1
// baseline (speedup 1.0000x reference)
#include <cuda_runtime.h>
#include <math.h>

#define N 4096
#define D 128
#define NS 75
#define TILE 4096
#define LOG2E 1.4426950408889634f

// ---------------- scratch (device globals; no runtime allocation) ----------
__device__ float g_d2[(size_t)N * N];      // 64 MB pairwise squared distances
__device__ float g_sq[N];                  // row squared norms
__device__ double g_sum_dist;
__device__ unsigned long long g_nz;
__device__ float g_c[NS];                  // log2e / sigma_j^2
__device__ double g_S1[NS], g_S2[NS];
__device__ float g_outc;                   // -log2e / sigma_opt^2

// ---------------- init: zero accumulators every launch ---------------------
__global__ void k_init() {
    int t = threadIdx.x;
    if (t == 0) { g_sum_dist = 0.0; g_nz = 0ULL; }
    if (t < NS) { g_S1[t] = 0.0; g_S2[t] = 0.0; }
}

// ---------------- row squared norms ----------------------------------------
__global__ void k_rowsq(const float* __restrict__ x) {
    int r = blockIdx.x;
    float v = x[(size_t)r * D + threadIdx.x];   // blockDim.x == 128 == D
    float s = v * v;
    #pragma unroll
    for (int o = 16; o; o >>= 1) s += __shfl_xor_sync(0xffffffffu, s, o);
    __shared__ float sh[4];
    int wid = threadIdx.x >> 5;
    if ((threadIdx.x & 31) == 0) sh[wid] = s;
    __syncthreads();
    if (threadIdx.x == 0) g_sq[r] = sh[0] + sh[1] + sh[2] + sh[3];
}

// ---------------- d2 GEMM (triangular blocks, mirrored stores) -------------
// 128x128 output tile per block, 256 threads, 8x8 per thread, fp32 FFMA.
__global__ __launch_bounds__(256) void k_d2(const float* __restrict__ x) {
    int b = blockIdx.x;
    float bf = (sqrtf(8.0f * (float)b + 1.0f) - 1.0f) * 0.5f;
    int bi = (int)bf;
    while ((bi + 1) * (bi + 2) / 2 <= b) bi++;
    while (bi * (bi + 1) / 2 > b) bi--;
    int bj = b - bi * (bi + 1) / 2;           // bi >= bj

    __shared__ float As[8][128];
    __shared__ float Bs[8][128];

    int tid = threadIdx.x;
    int tx = tid & 15;          // 0..15 (N dir)
    int ty = tid >> 4;          // 0..15 (M dir)
    int lr = tid >> 1;          // load row 0..127
    int lc = (tid & 1) * 4;     // load col offset 0 or 4

    const float* Ab = x + (size_t)bi * 128 * D;
    const float* Bb = x + (size_t)bj * 128 * D;

    float acc[8][8];
    #pragma unroll
    for (int m = 0; m < 8; m++)
        #pragma unroll
        for (int n = 0; n < 8; n++) acc[m][n] = 0.0f;

    for (int k0 = 0; k0 < D; k0 += 8) {
        float4 av = *(const float4*)(Ab + (size_t)lr * D + k0 + lc);
        float4 bv = *(const float4*)(Bb + (size_t)lr * D + k0 + lc);
        As[lc + 0][lr] = av.x; As[lc + 1][lr] = av.y;
        As[lc + 2][lr] = av.z; As[lc + 3][lr] = av.w;
        Bs[lc + 0][lr] = bv.x; Bs[lc + 1][lr] = bv.y;
        Bs[lc + 2][lr] = bv.z; Bs[lc + 3][lr] = bv.w;
        __syncthreads();
        #pragma unroll
        for (int k = 0; k < 8; k++) {
            float a[8], bb[8];
            #pragma unroll
            for (int m = 0; m < 8; m++) a[m] = As[k][ty * 8 + m];
            #pragma unroll
            for (int n = 0; n < 8; n++) bb[n] = Bs[k][tx * 8 + n];
            #pragma unroll
            for (int m = 0; m < 8; m++)
                #pragma unroll
                for (int n = 0; n < 8; n++)
                    acc[m][n] = fmaf(a[m], bb[n], acc[m][n]);
        }
        __syncthreads();
    }

    int row0 = bi * 128 + ty * 8;
    int col0 = bj * 128 + tx * 8;
    float sqi[8], sqj[8];
    #pragma unroll
    for (int m = 0; m < 8; m++) sqi[m] = g_sq[row0 + m];
    #pragma unroll
    for (int n = 0; n < 8; n++) sqj[n] = g_sq[col0 + n];

    float sd = 0.0f;
    int cnt = 0;
    #pragma unroll
    for (int m = 0; m < 8; m++) {
        float v[8];
        #pragma unroll
        for (int n = 0; n < 8; n++) {
            float dd = fmaxf(sqi[m] + sqj[n] - 2.0f * acc[m][n], 0.0f);
            v[n] = dd;
            if (dd > 0.0f) { sd += sqrtf(dd); cnt++; }
        }
        float4* p = (float4*)&g_d2[(size_t)(row0 + m) * N + col0];
        p[0] = make_float4(v[0], v[1], v[2], v[3]);
        p[1] = make_float4(v[4], v[5], v[6], v[7]);
    }
    if (bi != bj) {   // mirrored writes (matrix is symmetric)
        #pragma unroll
        for (int n = 0; n < 8; n++) {
            float t[8];
            #pragma unroll
            for (int m = 0; m < 8; m++)
                t[m] = fmaxf(sqi[m] + sqj[n] - 2.0f * acc[m][n], 0.0f);
            float4* p = (float4*)&g_d2[(size_t)(col0 + n) * N + row0];
            p[0] = make_float4(t[0], t[1], t[2], t[3]);
            p[1] = make_float4(t[4], t[5], t[6], t[7]);
        }
    }

    // stats reduction (off-diagonal tiles counted twice via weight)
    #pragma unroll
    for (int o = 16; o; o >>= 1) {
        sd  += __shfl_xor_sync(0xffffffffu, sd, o);
        cnt += __shfl_xor_sync(0xffffffffu, cnt, o);
    }
    __shared__ float ssd[8];
    __shared__ int   scn[8];
    int wid = tid >> 5;
    if ((tid & 31) == 0) { ssd[wid] = sd; scn[wid] = cnt; }
    __syncthreads();
    if (tid == 0) {
        float S = 0.0f; long long C = 0;
        #pragma unroll
        for (int i = 0; i < 8; i++) { S += ssd[i]; C += scn[i]; }
        double w = (bi == bj) ? 1.0 : 2.0;
        atomicAdd(&g_sum_dist, w * (double)S);
        atomicAdd(&g_nz, (unsigned long long)((bi == bj ? 1 : 2) * C));
    }
}

// ---------------- sigma grid setup -----------------------------------------
__global__ void k_setup() {
    if (threadIdx.x == 0) {
        float mean = (float)(g_sum_dist / (double)g_nz);
        float lo = 0.1f * mean;
        float hi = 10.0f * mean;
        float st = (hi - lo) / (float)NS;
        for (int j = 0; j < NS; j++) {
            float s = lo + st * (float)j;
            g_c[j] = LOG2E / (s * s);
        }
    }
}

// ---------------- sigma sweep: S1(t)=sum K*L, S2(t)=sum K^2 ----------------
// One block = TILE elements cached in SMEM. Sigmas interleaved across warps
// (j = warp + 8*jj, padded to 10 slots). 1 MUFU.EX2 + 3 FMA per elem-sigma.
__global__ __launch_bounds__(256) void k_sweep(const float* __restrict__ L) {
    __shared__ float sD[TILE];
    __shared__ float sL[TILE];
    __shared__ float sc[NS];

    int tid = threadIdx.x;
    if (tid < NS) sc[tid] = g_c[tid];

    size_t base = (size_t)blockIdx.x * TILE;
    const float4* gD = (const float4*)(g_d2 + base);
    const float4* gL = (const float4*)(L + base);
    #pragma unroll
    for (int i = tid; i < TILE / 4; i += 256) {
        float4 d = gD[i];
        float4 l = gL[i];
        ((float4*)sD)[i] = make_float4(-d.x, -d.y, -d.z, -d.w);
        ((float4*)sL)[i] = l;
    }
    __syncthreads();

    int w = tid >> 5, lane = tid & 31;
    float c[10], a1[10], a2[10];
    #pragma unroll
    for (int j = 0; j < 10; j++) {
        int idx = w + 8 * j;
        c[j] = (idx < NS) ? sc[idx] : 0.0f;
        a1[j] = 0.0f; a2[j] = 0.0f;
    }

    for (int e = lane; e < TILE; e += 32) {
        float md2 = sD[e];
        float lw  = sL[e];
        #pragma unroll
        for (int j = 0; j < 10; j++) {
            float K;
            asm("ex2.approx.ftz.f32 %0, %1;" : "=f"(K) : "f"(md2 * c[j]));
            a1[j] = fmaf(K, lw, a1[j]);
            a2[j] = fmaf(K, K,  a2[j]);
        }
    }

    #pragma unroll
    for (int j = 0; j < 10; j++) {
        int idx = w + 8 * j;
        float v1 = a1[j], v2 = a2[j];
        #pragma unroll
        for (int o = 16; o; o >>= 1) {
            v1 += __shfl_xor_sync(0xffffffffu, v1, o);
            v2 += __shfl_xor_sync(0xffffffffu, v2, o);
        }
        if (idx < NS && lane == 0) {
            atomicAdd(&g_S1[idx], (double)v1);
            atomicAdd(&g_S2[idx], (double)v2);
        }
    }
}

// ---------------- argmax (label_norm is a constant factor -> dropped) ------
__global__ void k_argmax() {
    if (threadIdx.x == 0) {
        double best = -1.0e300;
        int bidx = 0;
        for (int j = 0; j < NS; j++) {
            double l = g_S1[j] / sqrt(g_S2[j]);
            if (l > best) { best = l; bidx = j; }   // strict > keeps FIRST max
        }
        g_outc = -g_c[bidx];
    }
}

// ---------------- output: A = exp(-d2/sigma^2)/n ---------------------------
__global__ __launch_bounds__(256) void k_out(float* __restrict__ out) {
    float cc = g_outc;
    const float inv_n = 1.0f / (float)N;
    size_t i = ((size_t)blockIdx.x * blockDim.x + threadIdx.x) * 4;
    float4 d = *(const float4*)(g_d2 + i);
    float4 r;
    asm("ex2.approx.ftz.f32 %0, %1;" : "=f"(r.x) : "f"(d.x * cc));
    asm("ex2.approx.ftz.f32 %0, %1;" : "=f"(r.y) : "f"(d.y * cc));
    asm("ex2.approx.ftz.f32 %0, %1;" : "=f"(r.z) : "f"(d.z * cc));
    asm("ex2.approx.ftz.f32 %0, %1;" : "=f"(r.w) : "f"(d.w * cc));
    r.x *= inv_n; r.y *= inv_n; r.z *= inv_n; r.w *= inv_n;
    *(float4*)(out + i) = r;
}

// ---------------- launch ----------------------------------------------------
extern "C" void kernel_launch(void* const* d_in, const int* in_sizes, int n_in,
                              void* d_out, int out_size) {
    (void)in_sizes; (void)n_in; (void)out_size;
    const float* x = (const float*)d_in[0];
    const float* L = (const float*)d_in[1];
    float* out = (float*)d_out;

    k_init<<<1, 128>>>();
    k_rowsq<<<N, 128>>>(x);
    k_d2<<<(32 * 33) / 2, 256>>>(x);               // 528 triangular tiles
    k_setup<<<1, 1>>>();
    k_sweep<<<(int)(((size_t)N * N) / TILE), 256>>>(L);   // 4096 blocks
    k_argmax<<<1, 1>>>();
    k_out<<<(N * N) / (256 * 4), 256>>>(out);      // 16384 blocks
}

// round 3
// speedup vs baseline: 1.4931x; 1.4931x over previous
#include <cuda_runtime.h>
#include <math.h>

#define N 4096
#define D 128
#define NS 75
#define LOG2E 1.4426950408889634f

// ---------------- scratch (device globals; no runtime allocation) ----------
__device__ float g_d2[(size_t)N * N];      // upper-triangle tiles + diagonal tiles
__device__ float g_sq[N];                  // row squared norms
__device__ double g_sum_dist;
__device__ unsigned long long g_nz;
__device__ double g_S1[NS], g_S2[NS];
__device__ float g_outc;                   // -log2e / sigma_opt^2

// ---------------- row squared norms (+ accumulator init) -------------------
__global__ void k_rowsq(const float* __restrict__ x) {
    int r = blockIdx.x;
    if (r == 0 && threadIdx.x == 0) { g_sum_dist = 0.0; g_nz = 0ULL; }
    float v = x[(size_t)r * D + threadIdx.x];   // blockDim.x == 128 == D
    float s = v * v;
    #pragma unroll
    for (int o = 16; o; o >>= 1) s += __shfl_xor_sync(0xffffffffu, s, o);
    __shared__ float sh[4];
    int wid = threadIdx.x >> 5;
    if ((threadIdx.x & 31) == 0) sh[wid] = s;
    __syncthreads();
    if (threadIdx.x == 0) g_sq[r] = sh[0] + sh[1] + sh[2] + sh[3];
}

// ---------------- d2 GEMM (triangular blocks, upper-triangle stores) -------
// 128x128 output tile per block, 256 threads, 8x8 per thread, fp32 FFMA.
__global__ __launch_bounds__(256) void k_d2(const float* __restrict__ x) {
    int b = blockIdx.x;
    float bf = (sqrtf(8.0f * (float)b + 1.0f) - 1.0f) * 0.5f;
    int bi = (int)bf;
    while ((bi + 1) * (bi + 2) / 2 <= b) bi++;
    while (bi * (bi + 1) / 2 > b) bi--;
    int bj = b - bi * (bi + 1) / 2;           // bi >= bj

    __shared__ float As[8][128];
    __shared__ float Bs[8][128];

    int tid = threadIdx.x;
    int tx = tid & 15;          // 0..15
    int ty = tid >> 4;          // 0..15
    int lr = tid >> 1;          // load row 0..127
    int lc = (tid & 1) * 4;     // load col offset 0 or 4

    const float* Ab = x + (size_t)bi * 128 * D;
    const float* Bb = x + (size_t)bj * 128 * D;

    float acc[8][8];
    #pragma unroll
    for (int m = 0; m < 8; m++)
        #pragma unroll
        for (int n = 0; n < 8; n++) acc[m][n] = 0.0f;

    for (int k0 = 0; k0 < D; k0 += 8) {
        float4 av = *(const float4*)(Ab + (size_t)lr * D + k0 + lc);
        float4 bv = *(const float4*)(Bb + (size_t)lr * D + k0 + lc);
        As[lc + 0][lr] = av.x; As[lc + 1][lr] = av.y;
        As[lc + 2][lr] = av.z; As[lc + 3][lr] = av.w;
        Bs[lc + 0][lr] = bv.x; Bs[lc + 1][lr] = bv.y;
        Bs[lc + 2][lr] = bv.z; Bs[lc + 3][lr] = bv.w;
        __syncthreads();
        #pragma unroll
        for (int k = 0; k < 8; k++) {
            float a[8], bb[8];
            #pragma unroll
            for (int m = 0; m < 8; m++) a[m] = As[k][ty * 8 + m];
            #pragma unroll
            for (int n = 0; n < 8; n++) bb[n] = Bs[k][tx * 8 + n];
            #pragma unroll
            for (int m = 0; m < 8; m++)
                #pragma unroll
                for (int n = 0; n < 8; n++)
                    acc[m][n] = fmaf(a[m], bb[n], acc[m][n]);
        }
        __syncthreads();
    }

    int row0 = bi * 128 + ty * 8;   // larger index block
    int col0 = bj * 128 + tx * 8;   // smaller index block
    float sqi[8], sqj[8];
    #pragma unroll
    for (int m = 0; m < 8; m++) sqi[m] = g_sq[row0 + m];
    #pragma unroll
    for (int n = 0; n < 8; n++) sqj[n] = g_sq[col0 + n];

    float sd = 0.0f;
    int cnt = 0;

    if (bi == bj) {
        // diagonal tile: store direct (tile contains its own mirror)
        #pragma unroll
        for (int m = 0; m < 8; m++) {
            float v[8];
            #pragma unroll
            for (int n = 0; n < 8; n++) {
                float dd = fmaxf(sqi[m] + sqj[n] - 2.0f * acc[m][n], 0.0f);
                v[n] = dd;
                if (dd > 0.0f) { sd += sqrtf(dd); cnt++; }
            }
            float4* p = (float4*)&g_d2[(size_t)(row0 + m) * N + col0];
            p[0] = make_float4(v[0], v[1], v[2], v[3]);
            p[1] = make_float4(v[4], v[5], v[6], v[7]);
        }
    } else {
        // off-diagonal: store ONLY the upper-triangle tile (rows=bj blk, cols=bi blk)
        #pragma unroll
        for (int n = 0; n < 8; n++) {
            float t[8];
            #pragma unroll
            for (int m = 0; m < 8; m++) {
                float dd = fmaxf(sqi[m] + sqj[n] - 2.0f * acc[m][n], 0.0f);
                t[m] = dd;
                if (dd > 0.0f) { sd += sqrtf(dd); cnt++; }
            }
            float4* p = (float4*)&g_d2[(size_t)(col0 + n) * N + row0];
            p[0] = make_float4(t[0], t[1], t[2], t[3]);
            p[1] = make_float4(t[4], t[5], t[6], t[7]);
        }
    }

    #pragma unroll
    for (int o = 16; o; o >>= 1) {
        sd  += __shfl_xor_sync(0xffffffffu, sd, o);
        cnt += __shfl_xor_sync(0xffffffffu, cnt, o);
    }
    __shared__ float ssd[8];
    __shared__ int   scn[8];
    int wid = tid >> 5;
    if ((tid & 31) == 0) { ssd[wid] = sd; scn[wid] = cnt; }
    __syncthreads();
    if (tid == 0) {
        float S = 0.0f; long long C = 0;
        #pragma unroll
        for (int i = 0; i < 8; i++) { S += ssd[i]; C += scn[i]; }
        double w = (bi == bj) ? 1.0 : 2.0;
        atomicAdd(&g_sum_dist, w * (double)S);
        atomicAdd(&g_nz, (unsigned long long)((bi == bj ? 1 : 2) * C));
    }
}

// ---------------- diagonal contribution (exact) + S1/S2 init ---------------
__global__ void k_diag(const float* __restrict__ L) {
    int j = blockIdx.x;                          // sigma index 0..74
    float mean = (float)(g_sum_dist / (double)g_nz);
    float lo = 0.1f * mean;
    float st = (10.0f * mean - lo) / (float)NS;
    float s = lo + st * (float)j;
    float c = LOG2E / (s * s);

    float s1 = 0.0f, s2 = 0.0f;
    for (int i = threadIdx.x; i < N; i += 256) {
        float d = g_d2[(size_t)i * N + i];
        float l = L[(size_t)i * N + i];
        float K = exp2f(-d * c);
        s1 = fmaf(K, l, s1);
        s2 = fmaf(K, K, s2);
    }
    #pragma unroll
    for (int o = 16; o; o >>= 1) {
        s1 += __shfl_xor_sync(0xffffffffu, s1, o);
        s2 += __shfl_xor_sync(0xffffffffu, s2, o);
    }
    __shared__ float sh1[8], sh2[8];
    int wid = threadIdx.x >> 5;
    if ((threadIdx.x & 31) == 0) { sh1[wid] = s1; sh2[wid] = s2; }
    __syncthreads();
    if (threadIdx.x == 0) {
        float a = 0.0f, bq = 0.0f;
        #pragma unroll
        for (int i = 0; i < 8; i++) { a += sh1[i]; bq += sh2[i]; }
        g_S1[j] = (double)a;            // non-atomic init; sweep adds on top
        g_S2[j] = (double)bq;
    }
}

// ---------------- sigma sweep over strict upper triangle (weight 2) --------
// Block p handles rows p and N-1-p (columns > row): exactly N-1 elements.
// Sigmas interleaved across 8 warps (10 slots/warp). 1 MUFU + 3 FMA per term.
__global__ __launch_bounds__(256) void k_sweep(const float* __restrict__ L) {
    __shared__ float sD[N];     // 4095 used
    __shared__ float sL[N];
    __shared__ float sc[80];

    int tid = threadIdx.x;
    int p = blockIdx.x;                    // 0..N/2-1
    int r0 = p, r1 = N - 1 - p;
    int len0 = N - 1 - r0;                 // row r0: cols r0+1..N-1
    int len1 = p;                          // row r1: cols r1+1..N-1
    int total = len0 + len1;               // == N-1

    const float* D0 = g_d2 + (size_t)r0 * N + (r0 + 1);
    const float* L0 = L    + (size_t)r0 * N + (r0 + 1);
    const float* D1 = g_d2 + (size_t)r1 * N + (r1 + 1);
    const float* L1 = L    + (size_t)r1 * N + (r1 + 1);

    for (int i = tid; i < len0; i += 256) { sD[i] = -D0[i]; sL[i] = L0[i]; }
    for (int i = tid; i < len1; i += 256) { sD[len0 + i] = -D1[i]; sL[len0 + i] = L1[i]; }

    if (tid < 80) {
        float mean = (float)(g_sum_dist / (double)g_nz);
        float lo = 0.1f * mean;
        float st = (10.0f * mean - lo) / (float)NS;
        float s = lo + st * (float)tid;
        sc[tid] = (tid < NS) ? LOG2E / (s * s) : 0.0f;
    }
    __syncthreads();

    int w = tid >> 5, lane = tid & 31;
    float c[10], a1[10], a2[10];
    #pragma unroll
    for (int j = 0; j < 10; j++) {
        c[j] = sc[w + 8 * j];
        a1[j] = 0.0f; a2[j] = 0.0f;
    }

    for (int e = lane; e < total; e += 32) {
        float md2 = sD[e];
        float lw  = sL[e];
        #pragma unroll
        for (int j = 0; j < 10; j++) {
            float K;
            asm("ex2.approx.ftz.f32 %0, %1;" : "=f"(K) : "f"(md2 * c[j]));
            a1[j] = fmaf(K, lw, a1[j]);
            a2[j] = fmaf(K, K,  a2[j]);
        }
    }

    #pragma unroll
    for (int j = 0; j < 10; j++) {
        int idx = w + 8 * j;
        float v1 = a1[j], v2 = a2[j];
        #pragma unroll
        for (int o = 16; o; o >>= 1) {
            v1 += __shfl_xor_sync(0xffffffffu, v1, o);
            v2 += __shfl_xor_sync(0xffffffffu, v2, o);
        }
        if (idx < NS && lane == 0) {
            atomicAdd(&g_S1[idx], 2.0 * (double)v1);   // upper counted twice
            atomicAdd(&g_S2[idx], 2.0 * (double)v2);
        }
    }
}

// ---------------- argmax (label_norm is sigma-independent -> dropped) ------
__global__ void k_argmax() {
    if (threadIdx.x == 0) {
        float mean = (float)(g_sum_dist / (double)g_nz);
        float lo = 0.1f * mean;
        float st = (10.0f * mean - lo) / (float)NS;
        double best = -1.0e300;
        int bidx = 0;
        for (int j = 0; j < NS; j++) {
            double l = g_S1[j] / sqrt(g_S2[j]);
            if (l > best) { best = l; bidx = j; }   // strict > keeps FIRST max
        }
        float s = lo + st * (float)bidx;
        g_outc = -LOG2E / (s * s);
    }
}

// ---------------- output: A = exp(-d2/sigma^2)/n, triangular + mirror ------
// Off-diagonal tiles processed as four 64x64 quadrants through a 64x65 smem
// transpose buffer (16.6 KB, under the 48 KB static limit).
__global__ __launch_bounds__(256) void k_out(float* __restrict__ out) {
    int b = blockIdx.x;
    float bf = (sqrtf(8.0f * (float)b + 1.0f) - 1.0f) * 0.5f;
    int bi = (int)bf;
    while ((bi + 1) * (bi + 2) / 2 <= b) bi++;
    while (bi * (bi + 1) / 2 > b) bi--;
    int bj = b - bi * (bi + 1) / 2;           // bi >= bj
    int tr = bj, tc = bi;                     // stored tile: rows tr*128, cols tc*128

    float cc = g_outc;
    const float inv_n = 1.0f / (float)N;
    int tid = threadIdx.x;

    if (tr == tc) {
        // diagonal tile: direct exp, no mirror
        #pragma unroll
        for (int it = 0; it < 16; it++) {
            int e = (it * 256 + tid) * 4;
            int row = e >> 7;
            int col = e & 127;
            size_t g = (size_t)(tr * 128 + row) * N + tc * 128 + col;
            float4 d = *(const float4*)(g_d2 + g);
            float4 r;
            asm("ex2.approx.ftz.f32 %0, %1;" : "=f"(r.x) : "f"(d.x * cc));
            asm("ex2.approx.ftz.f32 %0, %1;" : "=f"(r.y) : "f"(d.y * cc));
            asm("ex2.approx.ftz.f32 %0, %1;" : "=f"(r.z) : "f"(d.z * cc));
            asm("ex2.approx.ftz.f32 %0, %1;" : "=f"(r.w) : "f"(d.w * cc));
            r.x *= inv_n; r.y *= inv_n; r.z *= inv_n; r.w *= inv_n;
            *(float4*)(out + g) = r;
        }
        return;
    }

    __shared__ float sT[64][65];
    #pragma unroll
    for (int q = 0; q < 4; q++) {
        int qr = q >> 1, qc = q & 1;
        int rbase = tr * 128 + qr * 64;       // stored quadrant origin
        int cbase = tc * 128 + qc * 64;
        // phase 1: exp + direct write + stage into smem
        #pragma unroll
        for (int it = 0; it < 4; it++) {
            int idx = it * 256 + tid;         // 0..1023 float4 slots
            int row = idx >> 4;               // 0..63
            int col = (idx & 15) * 4;         // 0..60
            size_t g = (size_t)(rbase + row) * N + cbase + col;
            float4 d = *(const float4*)(g_d2 + g);
            float4 r;
            asm("ex2.approx.ftz.f32 %0, %1;" : "=f"(r.x) : "f"(d.x * cc));
            asm("ex2.approx.ftz.f32 %0, %1;" : "=f"(r.y) : "f"(d.y * cc));
            asm("ex2.approx.ftz.f32 %0, %1;" : "=f"(r.z) : "f"(d.z * cc));
            asm("ex2.approx.ftz.f32 %0, %1;" : "=f"(r.w) : "f"(d.w * cc));
            r.x *= inv_n; r.y *= inv_n; r.z *= inv_n; r.w *= inv_n;
            *(float4*)(out + g) = r;
            sT[row][col + 0] = r.x; sT[row][col + 1] = r.y;
            sT[row][col + 2] = r.z; sT[row][col + 3] = r.w;
        }
        __syncthreads();
        // phase 2: transposed quadrant -> mirror tile (tc,tr), quadrant (qc,qr)
        #pragma unroll
        for (int it = 0; it < 4; it++) {
            int idx = it * 256 + tid;
            int row = idx >> 4;               // row in mirror quadrant
            int col = (idx & 15) * 4;
            size_t g = (size_t)(cbase + row) * N + rbase + col;
            float4 r = make_float4(sT[col + 0][row], sT[col + 1][row],
                                   sT[col + 2][row], sT[col + 3][row]);
            *(float4*)(out + g) = r;
        }
        __syncthreads();
    }
}

// ---------------- launch ----------------------------------------------------
extern "C" void kernel_launch(void* const* d_in, const int* in_sizes, int n_in,
                              void* d_out, int out_size) {
    (void)in_sizes; (void)n_in; (void)out_size;
    const float* x = (const float*)d_in[0];
    const float* L = (const float*)d_in[1];
    float* out = (float*)d_out;

    k_rowsq<<<N, 128>>>(x);
    k_d2<<<(32 * 33) / 2, 256>>>(x);          // 528 triangular tiles
    k_diag<<<NS, 256>>>(L);                   // exact diagonal + S1/S2 init
    k_sweep<<<N / 2, 256>>>(L);               // 2048 balanced triangle blocks
    k_argmax<<<1, 1>>>();
    k_out<<<(32 * 33) / 2, 256>>>(out);       // triangular tiles + mirrors
}

// round 4
// speedup vs baseline: 1.5803x; 1.0585x over previous
#include <cuda_runtime.h>
#include <math.h>

#define N 4096
#define D 128
#define NS 75
#define LOG2E 1.4426950408889634f

// ---------------- scratch (device globals; no runtime allocation) ----------
__device__ float g_d2[(size_t)N * N];      // upper-triangle tiles + diagonal tiles

struct Accum {
    double sum_dist;
    unsigned long long nz;
    double S1[NS];
    double S2[NS];
};
__device__ Accum g_acc;                    // zeroed via cudaMemsetAsync per launch

// ---------------- d2 GEMM (triangular blocks, fused row norms) -------------
// 128x128 output tile per block, 256 threads, 8x8 per thread, fp32 FFMA.
// Row squared norms computed from the loaded tiles (no separate pass).
__global__ __launch_bounds__(256) void k_d2(const float* __restrict__ x) {
    int b = blockIdx.x;
    float bf = (sqrtf(8.0f * (float)b + 1.0f) - 1.0f) * 0.5f;
    int bi = (int)bf;
    while ((bi + 1) * (bi + 2) / 2 <= b) bi++;
    while (bi * (bi + 1) / 2 > b) bi--;
    int bj = b - bi * (bi + 1) / 2;           // bi >= bj

    __shared__ float As[8][128];
    __shared__ float Bs[8][128];

    int tid = threadIdx.x;
    int tx = tid & 15;          // 0..15
    int ty = tid >> 4;          // 0..15
    int lr = tid >> 1;          // load row 0..127
    int lc = (tid & 1) * 4;     // load col offset 0 or 4

    const float* Ab = x + (size_t)bi * 128 * D;
    const float* Bb = x + (size_t)bj * 128 * D;

    float acc[8][8];
    #pragma unroll
    for (int m = 0; m < 8; m++)
        #pragma unroll
        for (int n = 0; n < 8; n++) acc[m][n] = 0.0f;

    float sa = 0.0f, sb = 0.0f;   // half-row squared-norm partials

    for (int k0 = 0; k0 < D; k0 += 8) {
        float4 av = *(const float4*)(Ab + (size_t)lr * D + k0 + lc);
        float4 bv = *(const float4*)(Bb + (size_t)lr * D + k0 + lc);
        sa = fmaf(av.x, av.x, fmaf(av.y, av.y, fmaf(av.z, av.z, fmaf(av.w, av.w, sa))));
        sb = fmaf(bv.x, bv.x, fmaf(bv.y, bv.y, fmaf(bv.z, bv.z, fmaf(bv.w, bv.w, sb))));
        As[lc + 0][lr] = av.x; As[lc + 1][lr] = av.y;
        As[lc + 2][lr] = av.z; As[lc + 3][lr] = av.w;
        Bs[lc + 0][lr] = bv.x; Bs[lc + 1][lr] = bv.y;
        Bs[lc + 2][lr] = bv.z; Bs[lc + 3][lr] = bv.w;
        __syncthreads();
        #pragma unroll
        for (int k = 0; k < 8; k++) {
            float a[8], bb[8];
            #pragma unroll
            for (int m = 0; m < 8; m++) a[m] = As[k][ty * 8 + m];
            #pragma unroll
            for (int n = 0; n < 8; n++) bb[n] = Bs[k][tx * 8 + n];
            #pragma unroll
            for (int m = 0; m < 8; m++)
                #pragma unroll
                for (int n = 0; n < 8; n++)
                    acc[m][n] = fmaf(a[m], bb[n], acc[m][n]);
        }
        __syncthreads();
    }

    // combine half-row partials (lanes tid, tid^1 share row lr) and publish
    sa += __shfl_xor_sync(0xffffffffu, sa, 1);
    sb += __shfl_xor_sync(0xffffffffu, sb, 1);
    float* sqA = &As[0][0];    // As/Bs no longer needed: reuse as norm storage
    float* sqB = &Bs[0][0];
    if ((tid & 1) == 0) { sqA[lr] = sa; sqB[lr] = sb; }
    __syncthreads();

    int row0 = bi * 128 + ty * 8;   // larger index block (A rows)
    int col0 = bj * 128 + tx * 8;   // smaller index block (B rows)
    float sqi[8], sqj[8];
    #pragma unroll
    for (int m = 0; m < 8; m++) sqi[m] = sqA[ty * 8 + m];
    #pragma unroll
    for (int n = 0; n < 8; n++) sqj[n] = sqB[tx * 8 + n];

    float sd = 0.0f;
    int cnt = 0;

    if (bi == bj) {
        // diagonal tile: store direct (tile contains its own mirror)
        #pragma unroll
        for (int m = 0; m < 8; m++) {
            float v[8];
            #pragma unroll
            for (int n = 0; n < 8; n++) {
                float dd = fmaxf(sqi[m] + sqj[n] - 2.0f * acc[m][n], 0.0f);
                v[n] = dd;
                if (dd > 0.0f) { sd += sqrtf(dd); cnt++; }
            }
            float4* p = (float4*)&g_d2[(size_t)(row0 + m) * N + col0];
            p[0] = make_float4(v[0], v[1], v[2], v[3]);
            p[1] = make_float4(v[4], v[5], v[6], v[7]);
        }
    } else {
        // off-diagonal: store ONLY the upper-triangle tile (rows=bj blk, cols=bi blk)
        #pragma unroll
        for (int n = 0; n < 8; n++) {
            float t[8];
            #pragma unroll
            for (int m = 0; m < 8; m++) {
                float dd = fmaxf(sqi[m] + sqj[n] - 2.0f * acc[m][n], 0.0f);
                t[m] = dd;
                if (dd > 0.0f) { sd += sqrtf(dd); cnt++; }
            }
            float4* p = (float4*)&g_d2[(size_t)(col0 + n) * N + row0];
            p[0] = make_float4(t[0], t[1], t[2], t[3]);
            p[1] = make_float4(t[4], t[5], t[6], t[7]);
        }
    }

    #pragma unroll
    for (int o = 16; o; o >>= 1) {
        sd  += __shfl_xor_sync(0xffffffffu, sd, o);
        cnt += __shfl_xor_sync(0xffffffffu, cnt, o);
    }
    __shared__ float ssd[8];
    __shared__ int   scn[8];
    int wid = tid >> 5;
    if ((tid & 31) == 0) { ssd[wid] = sd; scn[wid] = cnt; }
    __syncthreads();
    if (tid == 0) {
        float S = 0.0f; long long C = 0;
        #pragma unroll
        for (int i = 0; i < 8; i++) { S += ssd[i]; C += scn[i]; }
        double w = (bi == bj) ? 1.0 : 2.0;
        atomicAdd(&g_acc.sum_dist, w * (double)S);
        atomicAdd(&g_acc.nz, (unsigned long long)((bi == bj ? 1 : 2) * C));
    }
}

// ---------------- sigma sweep (strict upper, weight 2) + fused diagonal ----
// Blocks 0..2047: rows p and N-1-p (cols > row) -> exactly N-1 elements each.
// Blocks 2048..2122: exact diagonal contribution for sigma j = bid-2048.
// 16 warps; warps 0..10 own 5 sigmas, warps 11..15 own 4 (75 exact, no waste).
__global__ __launch_bounds__(512, 3) void k_sweep(const float* __restrict__ L) {
    __shared__ float2 sDL[N];    // (-d2, L); 4095 used
    __shared__ float sc[80];

    int tid = threadIdx.x;
    int bid = blockIdx.x;

    if (tid < 80) {
        float mean = (float)(g_acc.sum_dist / (double)g_acc.nz);
        float lo = 0.1f * mean;
        float st = (10.0f * mean - lo) / (float)NS;
        float s = lo + st * (float)tid;
        sc[tid] = (tid < NS) ? LOG2E / (s * s) : 0.0f;
    }

    int w = tid >> 5, lane = tid & 31;

    if (bid >= N / 2) {
        // ---- diagonal block for sigma j ----
        __syncthreads();
        int j = bid - N / 2;
        float c = sc[j];
        float s1 = 0.0f, s2 = 0.0f;
        for (int i = tid; i < N; i += 512) {
            float d = g_d2[(size_t)i * N + i];
            float l = L[(size_t)i * N + i];
            float K = exp2f(-d * c);
            s1 = fmaf(K, l, s1);
            s2 = fmaf(K, K, s2);
        }
        #pragma unroll
        for (int o = 16; o; o >>= 1) {
            s1 += __shfl_xor_sync(0xffffffffu, s1, o);
            s2 += __shfl_xor_sync(0xffffffffu, s2, o);
        }
        __shared__ float sh1[16], sh2[16];
        if (lane == 0) { sh1[w] = s1; sh2[w] = s2; }
        __syncthreads();
        if (tid == 0) {
            float a = 0.0f, bq = 0.0f;
            #pragma unroll
            for (int i = 0; i < 16; i++) { a += sh1[i]; bq += sh2[i]; }
            atomicAdd(&g_acc.S1[j], (double)a);
            atomicAdd(&g_acc.S2[j], (double)bq);
        }
        return;
    }

    // ---- triangle sweep block ----
    int p = bid;
    int r0 = p, r1 = N - 1 - p;
    int len0 = N - 1 - r0;                 // row r0: cols r0+1..N-1
    int len1 = p;                          // row r1: cols r1+1..N-1
    int total = N - 1;

    const float* D0 = g_d2 + (size_t)r0 * N + (r0 + 1);
    const float* L0 = L    + (size_t)r0 * N + (r0 + 1);
    const float* D1 = g_d2 + (size_t)r1 * N + (r1 + 1);
    const float* L1 = L    + (size_t)r1 * N + (r1 + 1);

    for (int i = tid; i < len0; i += 512) sDL[i] = make_float2(-D0[i], L0[i]);
    for (int i = tid; i < len1; i += 512) sDL[len0 + i] = make_float2(-D1[i], L1[i]);
    __syncthreads();

    bool has5 = (w < 11);
    float c[5], a1[5], a2[5];
    #pragma unroll
    for (int j = 0; j < 4; j++) { c[j] = sc[w + 16 * j]; a1[j] = 0.0f; a2[j] = 0.0f; }
    c[4] = has5 ? sc[64 + w] : 0.0f;
    a1[4] = 0.0f; a2[4] = 0.0f;

    if (has5) {
        for (int e = lane; e < total; e += 32) {
            float2 dl = sDL[e];
            #pragma unroll
            for (int j = 0; j < 5; j++) {
                float K;
                asm("ex2.approx.ftz.f32 %0, %1;" : "=f"(K) : "f"(dl.x * c[j]));
                a1[j] = fmaf(K, dl.y, a1[j]);
                a2[j] = fmaf(K, K,  a2[j]);
            }
        }
    } else {
        for (int e = lane; e < total; e += 32) {
            float2 dl = sDL[e];
            #pragma unroll
            for (int j = 0; j < 4; j++) {
                float K;
                asm("ex2.approx.ftz.f32 %0, %1;" : "=f"(K) : "f"(dl.x * c[j]));
                a1[j] = fmaf(K, dl.y, a1[j]);
                a2[j] = fmaf(K, K,  a2[j]);
            }
        }
    }

    #pragma unroll
    for (int j = 0; j < 5; j++) {
        float v1 = a1[j], v2 = a2[j];
        #pragma unroll
        for (int o = 16; o; o >>= 1) {
            v1 += __shfl_xor_sync(0xffffffffu, v1, o);
            v2 += __shfl_xor_sync(0xffffffffu, v2, o);
        }
        if (lane == 0 && (j < 4 || has5)) {
            int idx = (j < 4) ? (w + 16 * j) : (64 + w);
            atomicAdd(&g_acc.S1[idx], 2.0 * (double)v1);   // upper counted twice
            atomicAdd(&g_acc.S2[idx], 2.0 * (double)v2);
        }
    }
}

// ---------------- output: A = exp(-d2/sigma^2)/n, triangular + mirror ------
// Fused argmax: every block recomputes it (deterministic, identical result).
// Off-diagonal tiles: four 64x64 quadrants through a 64x65 smem buffer.
__global__ __launch_bounds__(256) void k_out(float* __restrict__ out) {
    __shared__ float s_cc;
    int tid = threadIdx.x;

    if (tid == 0) {
        float mean = (float)(g_acc.sum_dist / (double)g_acc.nz);
        float lo = 0.1f * mean;
        float st = (10.0f * mean - lo) / (float)NS;
        float best = -1.0e30f;
        int bidx = 0;
        #pragma unroll 1
        for (int j = 0; j < NS; j++) {
            float l = (float)g_acc.S1[j] / sqrtf((float)g_acc.S2[j]);
            if (l > best) { best = l; bidx = j; }   // strict > keeps FIRST max
        }
        float s = lo + st * (float)bidx;
        s_cc = -LOG2E / (s * s);
    }
    __syncthreads();
    float cc = s_cc;
    const float inv_n = 1.0f / (float)N;

    int b = blockIdx.x;
    float bf = (sqrtf(8.0f * (float)b + 1.0f) - 1.0f) * 0.5f;
    int bi = (int)bf;
    while ((bi + 1) * (bi + 2) / 2 <= b) bi++;
    while (bi * (bi + 1) / 2 > b) bi--;
    int bj = b - bi * (bi + 1) / 2;           // bi >= bj
    int tr = bj, tc = bi;                     // stored tile: rows tr*128, cols tc*128

    if (tr == tc) {
        // diagonal tile: direct exp, no mirror
        #pragma unroll
        for (int it = 0; it < 16; it++) {
            int e = (it * 256 + tid) * 4;
            int row = e >> 7;
            int col = e & 127;
            size_t g = (size_t)(tr * 128 + row) * N + tc * 128 + col;
            float4 d = *(const float4*)(g_d2 + g);
            float4 r;
            asm("ex2.approx.ftz.f32 %0, %1;" : "=f"(r.x) : "f"(d.x * cc));
            asm("ex2.approx.ftz.f32 %0, %1;" : "=f"(r.y) : "f"(d.y * cc));
            asm("ex2.approx.ftz.f32 %0, %1;" : "=f"(r.z) : "f"(d.z * cc));
            asm("ex2.approx.ftz.f32 %0, %1;" : "=f"(r.w) : "f"(d.w * cc));
            r.x *= inv_n; r.y *= inv_n; r.z *= inv_n; r.w *= inv_n;
            *(float4*)(out + g) = r;
        }
        return;
    }

    __shared__ float sT[64][65];
    #pragma unroll
    for (int q = 0; q < 4; q++) {
        int qr = q >> 1, qc = q & 1;
        int rbase = tr * 128 + qr * 64;       // stored quadrant origin
        int cbase = tc * 128 + qc * 64;
        // phase 1: exp + direct write + stage into smem
        #pragma unroll
        for (int it = 0; it < 4; it++) {
            int idx = it * 256 + tid;         // 0..1023 float4 slots
            int row = idx >> 4;               // 0..63
            int col = (idx & 15) * 4;         // 0..60
            size_t g = (size_t)(rbase + row) * N + cbase + col;
            float4 d = *(const float4*)(g_d2 + g);
            float4 r;
            asm("ex2.approx.ftz.f32 %0, %1;" : "=f"(r.x) : "f"(d.x * cc));
            asm("ex2.approx.ftz.f32 %0, %1;" : "=f"(r.y) : "f"(d.y * cc));
            asm("ex2.approx.ftz.f32 %0, %1;" : "=f"(r.z) : "f"(d.z * cc));
            asm("ex2.approx.ftz.f32 %0, %1;" : "=f"(r.w) : "f"(d.w * cc));
            r.x *= inv_n; r.y *= inv_n; r.z *= inv_n; r.w *= inv_n;
            *(float4*)(out + g) = r;
            sT[row][col + 0] = r.x; sT[row][col + 1] = r.y;
            sT[row][col + 2] = r.z; sT[row][col + 3] = r.w;
        }
        __syncthreads();
        // phase 2: transposed quadrant -> mirror tile (tc,tr), quadrant (qc,qr)
        #pragma unroll
        for (int it = 0; it < 4; it++) {
            int idx = it * 256 + tid;
            int row = idx >> 4;               // row in mirror quadrant
            int col = (idx & 15) * 4;
            size_t g = (size_t)(cbase + row) * N + rbase + col;
            float4 r = make_float4(sT[col + 0][row], sT[col + 1][row],
                                   sT[col + 2][row], sT[col + 3][row]);
            *(float4*)(out + g) = r;
        }
        __syncthreads();
    }
}

// ---------------- launch ----------------------------------------------------
extern "C" void kernel_launch(void* const* d_in, const int* in_sizes, int n_in,
                              void* d_out, int out_size) {
    (void)in_sizes; (void)n_in; (void)out_size;
    const float* x = (const float*)d_in[0];
    const float* L = (const float*)d_in[1];
    float* out = (float*)d_out;

    void* acc_ptr = nullptr;
    cudaGetSymbolAddress(&acc_ptr, g_acc);
    cudaMemsetAsync(acc_ptr, 0, sizeof(Accum));    // zero all accumulators

    k_d2<<<(32 * 33) / 2, 256>>>(x);          // 528 triangular tiles (+row norms)
    k_sweep<<<N / 2 + NS, 512>>>(L);          // 2048 triangle + 75 diagonal blocks
    k_out<<<(32 * 33) / 2, 256>>>(out);       // tiles + mirrors (+inline argmax)
}